// round 16
// baseline (speedup 1.0000x reference)
#include <cuda_runtime.h>
#include <cstdint>

// Problem constants
#define T 4
#define E 250000
#define D 128
#define B 4096
#define L 50

// ============================================================================
// FINAL — at the workload roofline (validated over 15 rounds):
//   * Per-replay DRAM traffic = unique-row floor: E(1-e^{-BL/E}) = 139.8k
//     unique rows/table x 512B x 4 tables + indices + output ~= 297MB.
//     Measured at this floor in every round since the table-phased layout
//     landed (R6). Cross-replay L2 pinning refuted twice.
//   * HBM bandwidth = random-512B-gather ceiling, ~5.7-6.2 TB/s depending on
//     run draw (+-4% run-to-run variance on identical binaries). Invariant
//     to occupancy (40-90%), access ordering (warp-sorted indices REGRESSED
//     via shfl-chain bubbles), cache policy, and load width (128/256-bit).
//   * kernel time ~= traffic / bandwidth ~= 48-52us; bench adds ~3.5us fixed
//     harness overhead.
// Mechanisms in this kernel:
//   1. Single-wave table-phased execution: 512 CTAs x 256 threads, all
//      co-resident; warp = bag. All warps sweep table 0, then 1, ... so the
//      live working set is ONE table's unique rows (~72MB) which fits L2
//      (126MB) -> duplicate-row gathers hit L2, DRAM sits at the floor.
//      (Unphased layouts measured ~337MB traffic: two tables live at once.)
//   2. evict_last policy on weight gathers keeps reused rows resident;
//      streaming .cs stores keep the write-once output out of L2.
//   3. All 50 bag indices preloaded with 2 coalesced loads + shfl broadcast;
//      NEXT phase's indices prefetched at the top of each phase so index
//      latency never serializes at table boundaries (best measured kernel
//      time of all variants: 47.87us).
//   4. 10 independent LDG.128 in flight per warp — latency hiding at the
//      ~28 warps/SM single-wave occupancy.
// ============================================================================

// 128-bit gather with L2 evict_last via cache-policy register.
__device__ __forceinline__ float4 ldg4_policy(const float4* p, uint64_t pol) {
    float4 v;
    asm("ld.global.nc.L2::cache_hint.v4.f32 {%0,%1,%2,%3}, [%4], %5;"
        : "=f"(v.x), "=f"(v.y), "=f"(v.z), "=f"(v.w)
        : "l"(p), "l"(pol));
    return v;
}

// Streaming 128-bit store (write-once output; don't pollute L2).
__device__ __forceinline__ void stg_cs4(float4* p, float4 v) {
    asm volatile("st.global.cs.v4.f32 [%0], {%1,%2,%3,%4};"
                 :: "l"(p), "f"(v.x), "f"(v.y), "f"(v.z), "f"(v.w));
}

__global__ __launch_bounds__(256, 4)
void embbag_kernel(const float4* __restrict__ weights4,
                   const int*    __restrict__ indices,
                   float4*       __restrict__ out4) {
    const int b = (blockIdx.x * blockDim.x + threadIdx.x) >> 5;  // bag = warp id
    const int lane = threadIdx.x & 31;
    if (b >= B) return;

    uint64_t pol;
    asm("createpolicy.fractional.L2::evict_last.b64 %0, 1.0;" : "=l"(pol));

    // Phase 0 indices (2 coalesced loads; distributed to the warp via shfl).
    const int* __restrict__ idx0 = indices + (size_t)b * L;
    int ia_n = __ldg(idx0 + lane);
    int ib_n = (lane < (L - 32)) ? __ldg(idx0 + 32 + lane) : 0;

    #pragma unroll
    for (int t = 0; t < T; t++) {
        const int ia = ia_n;
        const int ib = ib_n;

        // Prefetch NEXT phase's indices; latency overlaps the gathers below.
        if (t + 1 < T) {
            const int* __restrict__ idxn = indices + ((size_t)(t + 1) * B + b) * L;
            ia_n = __ldg(idxn + lane);
            ib_n = (lane < (L - 32)) ? __ldg(idxn + 32 + lane) : 0;
        }

        const float4* __restrict__ wt = weights4 + (size_t)t * E * (D / 4);

        float4 a0 = make_float4(0.f, 0.f, 0.f, 0.f);
        float4 a1 = make_float4(0.f, 0.f, 0.f, 0.f);

        // 5 groups of 10 fully independent LDG.128.
        #pragma unroll
        for (int l = 0; l < L; l += 10) {
            const float4* p[10];
            #pragma unroll
            for (int k = 0; k < 10; k++) {
                const int ll = l + k;       // compile-time resolvable selector
                const int j = (ll < 32) ? __shfl_sync(0xffffffffu, ia, ll)
                                        : __shfl_sync(0xffffffffu, ib, ll - 32);
                p[k] = wt + (size_t)j * (D / 4) + lane;
            }
            float4 r[10];
            #pragma unroll
            for (int k = 0; k < 10; k++) r[k] = ldg4_policy(p[k], pol);

            #pragma unroll
            for (int k = 0; k < 10; k += 2) {
                a0.x += r[k].x;   a0.y += r[k].y;   a0.z += r[k].z;   a0.w += r[k].w;
                a1.x += r[k+1].x; a1.y += r[k+1].y; a1.z += r[k+1].z; a1.w += r[k+1].w;
            }
        }

        const float4 acc = make_float4(a0.x + a1.x, a0.y + a1.y,
                                       a0.z + a1.z, a0.w + a1.w);

        // out[b][t*D + lane*4 .. +3], coalesced 512B per warp
        stg_cs4(out4 + ((size_t)b * T + t) * (D / 4) + lane, acc);
    }
}

extern "C" void kernel_launch(void* const* d_in, const int* in_sizes, int n_in,
                              void* d_out, int out_size) {
    const float4* weights4 = (const float4*)d_in[0];  // [T, E, D] fp32
    const int*    indices  = (const int*)d_in[1];     // [T, B, L] int32
    float4*       out4     = (float4*)d_out;          // [B, T*D] fp32

    // 4096 bags, one warp each -> 512 CTAs of 8 warps: single co-resident wave,
    // all CTAs sweep tables in loose lockstep (phase working set fits L2).
    const int threads = 256;
    const int blocks = (B * 32) / threads;            // 512
    embbag_kernel<<<blocks, threads>>>(weights4, indices, out4);
}

// round 17
// speedup vs baseline: 1.0124x; 1.0124x over previous
#include <cuda_runtime.h>
#include <cstdint>

// Problem constants
#define T 4
#define E 250000
#define D 128
#define B 4096
#define L 50

// ============================================================================
// FINAL — at the workload roofline (validated over 16 rounds):
//   * Per-replay DRAM traffic = unique-row floor (~295MB: 139.8k unique
//     rows/table x 512B x 4 + indices + output). At floor every run since
//     the table-phased layout landed. Sub-floor attempts (cross-replay L2
//     pinning x2) refuted by measurement.
//   * HBM bandwidth = random-512B-gather ceiling (~5.7-6.2 TB/s run-to-run;
//     +-4% variance on identical binaries). Invariant to occupancy 40-90%,
//     access ordering (warp-sorting REGRESSED -24%), cache policy, load
//     width, CTA shape. TMA is LTS-cap-equivalent -> no alternate path.
//   * kernel time ~= traffic / bandwidth (48-52us); bench adds ~3us fixed
//     harness overhead.
// Mechanisms:
//   1. Single-wave table-phased execution: 512 CTAs x 256 threads, all
//      co-resident; warp = bag. All warps sweep table 0, then 1, ... so the
//      live working set is ONE table's unique rows (~72MB), fitting L2
//      (126MB) -> duplicate-row gathers hit L2, DRAM sits at the floor
//      (unphased layouts measured ~337MB: two tables live at once).
//   2. evict_last policy on weight gathers keeps reused rows resident;
//      streaming .cs stores keep the write-once output out of L2.
//   3. All 50 bag indices preloaded with 2 coalesced loads + shfl broadcast;
//      NEXT phase's indices prefetched at the top of each phase so index
//      latency never serializes at table boundaries.
//   4. 10 independent LDG.128 in flight per warp — latency hiding at the
//      ~28 warps/SM single-wave occupancy.
// ============================================================================

// 128-bit gather with L2 evict_last via cache-policy register.
__device__ __forceinline__ float4 ldg4_policy(const float4* p, uint64_t pol) {
    float4 v;
    asm("ld.global.nc.L2::cache_hint.v4.f32 {%0,%1,%2,%3}, [%4], %5;"
        : "=f"(v.x), "=f"(v.y), "=f"(v.z), "=f"(v.w)
        : "l"(p), "l"(pol));
    return v;
}

// Streaming 128-bit store (write-once output; don't pollute L2).
__device__ __forceinline__ void stg_cs4(float4* p, float4 v) {
    asm volatile("st.global.cs.v4.f32 [%0], {%1,%2,%3,%4};"
                 :: "l"(p), "f"(v.x), "f"(v.y), "f"(v.z), "f"(v.w));
}

__global__ __launch_bounds__(256, 4)
void embbag_kernel(const float4* __restrict__ weights4,
                   const int*    __restrict__ indices,
                   float4*       __restrict__ out4) {
    const int b = (blockIdx.x * blockDim.x + threadIdx.x) >> 5;  // bag = warp id
    const int lane = threadIdx.x & 31;
    if (b >= B) return;

    uint64_t pol;
    asm("createpolicy.fractional.L2::evict_last.b64 %0, 1.0;" : "=l"(pol));

    // Phase 0 indices (2 coalesced loads; distributed to the warp via shfl).
    const int* __restrict__ idx0 = indices + (size_t)b * L;
    int ia_n = __ldg(idx0 + lane);
    int ib_n = (lane < (L - 32)) ? __ldg(idx0 + 32 + lane) : 0;

    #pragma unroll
    for (int t = 0; t < T; t++) {
        const int ia = ia_n;
        const int ib = ib_n;

        // Prefetch NEXT phase's indices; latency overlaps the gathers below.
        if (t + 1 < T) {
            const int* __restrict__ idxn = indices + ((size_t)(t + 1) * B + b) * L;
            ia_n = __ldg(idxn + lane);
            ib_n = (lane < (L - 32)) ? __ldg(idxn + 32 + lane) : 0;
        }

        const float4* __restrict__ wt = weights4 + (size_t)t * E * (D / 4);

        float4 a0 = make_float4(0.f, 0.f, 0.f, 0.f);
        float4 a1 = make_float4(0.f, 0.f, 0.f, 0.f);

        // 5 groups of 10 fully independent LDG.128.
        #pragma unroll
        for (int l = 0; l < L; l += 10) {
            const float4* p[10];
            #pragma unroll
            for (int k = 0; k < 10; k++) {
                const int ll = l + k;       // compile-time resolvable selector
                const int j = (ll < 32) ? __shfl_sync(0xffffffffu, ia, ll)
                                        : __shfl_sync(0xffffffffu, ib, ll - 32);
                p[k] = wt + (size_t)j * (D / 4) + lane;
            }
            float4 r[10];
            #pragma unroll
            for (int k = 0; k < 10; k++) r[k] = ldg4_policy(p[k], pol);

            #pragma unroll
            for (int k = 0; k < 10; k += 2) {
                a0.x += r[k].x;   a0.y += r[k].y;   a0.z += r[k].z;   a0.w += r[k].w;
                a1.x += r[k+1].x; a1.y += r[k+1].y; a1.z += r[k+1].z; a1.w += r[k+1].w;
            }
        }

        const float4 acc = make_float4(a0.x + a1.x, a0.y + a1.y,
                                       a0.z + a1.z, a0.w + a1.w);

        // out[b][t*D + lane*4 .. +3], coalesced 512B per warp
        stg_cs4(out4 + ((size_t)b * T + t) * (D / 4) + lane, acc);
    }
}

extern "C" void kernel_launch(void* const* d_in, const int* in_sizes, int n_in,
                              void* d_out, int out_size) {
    const float4* weights4 = (const float4*)d_in[0];  // [T, E, D] fp32
    const int*    indices  = (const int*)d_in[1];     // [T, B, L] int32
    float4*       out4     = (float4*)d_out;          // [B, T*D] fp32

    // 4096 bags, one warp each -> 512 CTAs of 8 warps: single co-resident wave,
    // all CTAs sweep tables in loose lockstep (phase working set fits L2).
    const int threads = 256;
    const int blocks = (B * 32) / threads;            // 512
    embbag_kernel<<<blocks, threads>>>(weights4, indices, out4);
}